// round 1
// baseline (speedup 1.0000x reference)
#include <cuda_runtime.h>
#include <cuda_bf16.h>
#include <math.h>

#define NAGT 1024
#define RNN  128
#define EMB  64
#define GCELLS 64   // 8x8
#define NMIX 20

// ---------------- device scratch (no allocations allowed) ----------------
__device__ float g_xin[NAGT * 128];          // [emb(64) | pool(64)] per agent
__device__ float g_Hs[NAGT * GCELLS * EMB];  // Hs[m][g][e], 16 MB
__device__ float g_gates[NAGT * 512];
__device__ float g_hn[NAGT * RNN];

// ---------------- K1: emb = relu(xoff @ W_emb^T + b_emb) ----------------
__global__ void k_emb(const float* __restrict__ xoff,
                      const float* __restrict__ W_emb,
                      const float* __restrict__ b_emb) {
    int idx = blockIdx.x * 256 + threadIdx.x;   // 1024*64
    if (idx >= NAGT * EMB) return;
    int n = idx >> 6, e = idx & 63;
    float v = b_emb[e];
    v = fmaf(xoff[2 * n + 0], W_emb[2 * e + 0], v);
    v = fmaf(xoff[2 * n + 1], W_emb[2 * e + 1], v);
    g_xin[n * 128 + e] = fmaxf(v, 0.0f);
}

// ---------------- K2: Hs[m,g,e] = sum_h h0[m,h] * W_soc[e, g*128+h] ------
// GEMM M=1024 (m) x N=64 (e, per-g) x K=128.  grid=(16 m-tiles, 64 g), 128 thr
__global__ void k_hs(const float* __restrict__ h0,
                     const float* __restrict__ Wsoc) {
    __shared__ float As[64][65];   // [m_local][k_local]
    __shared__ float Bs[64][65];   // [e][k_local]
    const int m0 = blockIdx.x * 64;
    const int g  = blockIdx.y;
    const int tid = threadIdx.x;           // 128 threads
    const int tx = tid & 15;               // e micro col group (4 cols)
    const int ty = tid >> 4;               // m micro row group (8 rows)

    float acc[8][4];
#pragma unroll
    for (int i = 0; i < 8; i++)
#pragma unroll
        for (int j = 0; j < 4; j++) acc[i][j] = 0.0f;

    for (int kc = 0; kc < 2; kc++) {
        const int kbase = kc * 64;
        // load A tile 64x64 (float4 global loads)
        for (int i = tid; i < 64 * 16; i += 128) {
            int r = i >> 4, c4 = i & 15;
            float4 v = *(const float4*)(h0 + (m0 + r) * 128 + kbase + c4 * 4);
            As[r][c4 * 4 + 0] = v.x; As[r][c4 * 4 + 1] = v.y;
            As[r][c4 * 4 + 2] = v.z; As[r][c4 * 4 + 3] = v.w;
        }
        // load B tile: W_soc[e, g*128 + kbase + c]
        for (int i = tid; i < 64 * 16; i += 128) {
            int r = i >> 4, c4 = i & 15;
            float4 v = *(const float4*)(Wsoc + r * 8192 + g * 128 + kbase + c4 * 4);
            Bs[r][c4 * 4 + 0] = v.x; Bs[r][c4 * 4 + 1] = v.y;
            Bs[r][c4 * 4 + 2] = v.z; Bs[r][c4 * 4 + 3] = v.w;
        }
        __syncthreads();
#pragma unroll 4
        for (int k = 0; k < 64; k++) {
            float a[8], b[4];
#pragma unroll
            for (int i = 0; i < 8; i++) a[i] = As[ty * 8 + i][k];
#pragma unroll
            for (int j = 0; j < 4; j++) b[j] = Bs[tx * 4 + j][k];
#pragma unroll
            for (int i = 0; i < 8; i++)
#pragma unroll
                for (int j = 0; j < 4; j++) acc[i][j] = fmaf(a[i], b[j], acc[i][j]);
        }
        __syncthreads();
    }
#pragma unroll
    for (int i = 0; i < 8; i++) {
        float4 v = make_float4(acc[i][0], acc[i][1], acc[i][2], acc[i][3]);
        *(float4*)&g_Hs[(m0 + ty * 8 + i) * 4096 + g * 64 + tx * 4] = v;
    }
}

// ---------------- K3: pool[n] = relu(b_soc + sum_m valid * Hs[m,cell,:]) --
// one block per agent, 256 threads = 4 groups x 64 lanes (e)
__global__ void k_pool(const float* __restrict__ xabs,
                       const float* __restrict__ b_soc) {
    __shared__ float sx[NAGT];
    __shared__ float sy[NAGT];
    __shared__ float red[4][64];
    const int n = blockIdx.x;
    const int tid = threadIdx.x;
    for (int i = tid; i < NAGT; i += 256) {
        sx[i] = xabs[2 * i + 0];
        sy[i] = xabs[2 * i + 1];
    }
    __syncthreads();
    const float xn = sx[n] - 0.2f;   // x[n] - NS/2
    const float yn = sy[n] - 0.2f;
    const int grp = tid >> 6;
    const int e   = tid & 63;
    float acc = 0.0f;
    const int mEnd = grp * 256 + 256;
    for (int m = grp * 256; m < mEnd; ++m) {
        float dx = sx[m] - xn;
        float dy = sy[m] - yn;
        if (m != n && dx >= 0.0f && dx < 0.4f && dy >= 0.0f && dy < 0.4f) {
            int cx = (int)floorf(dx / 0.4f * 8.0f);
            int cy = (int)floorf(dy / 0.4f * 8.0f);
            if (cx >= 0 && cx < 8 && cy >= 0 && cy < 8) {
                acc += g_Hs[m * 4096 + (cx + cy * 8) * 64 + e];
            }
        }
    }
    red[grp][e] = acc;
    __syncthreads();
    if (tid < 64) {
        float s = red[0][tid] + red[1][tid] + red[2][tid] + red[3][tid] + b_soc[tid];
        g_xin[n * 128 + 64 + tid] = fmaxf(s, 0.0f);
    }
}

// ---------------- K4a: gates = [xin|h] @ [W_ih|W_hh]^T ------------------
// GEMM M=1024 x N=512 x K=256. grid=(16,8), 128 threads, micro 8x4
__global__ void k_gates(const float* __restrict__ h0,
                        const float* __restrict__ Wih,
                        const float* __restrict__ Whh) {
    __shared__ float As[64][65];
    __shared__ float Bs[64][65];
    const int m0 = blockIdx.x * 64;
    const int j0 = blockIdx.y * 64;
    const int tid = threadIdx.x;
    const int tx = tid & 15;
    const int ty = tid >> 4;

    float acc[8][4];
#pragma unroll
    for (int i = 0; i < 8; i++)
#pragma unroll
        for (int j = 0; j < 4; j++) acc[i][j] = 0.0f;

    for (int kc = 0; kc < 4; kc++) {
        const int kg = kc * 64;
        const float* Asrc = (kg < 128) ? (g_xin + kg) : (h0 + (kg - 128));
        const float* Bsrc = (kg < 128) ? (Wih + kg) : (Whh + (kg - 128));
        for (int i = tid; i < 64 * 16; i += 128) {
            int r = i >> 4, c4 = i & 15;
            float4 v = *(const float4*)(Asrc + (m0 + r) * 128 + c4 * 4);
            As[r][c4 * 4 + 0] = v.x; As[r][c4 * 4 + 1] = v.y;
            As[r][c4 * 4 + 2] = v.z; As[r][c4 * 4 + 3] = v.w;
        }
        for (int i = tid; i < 64 * 16; i += 128) {
            int r = i >> 4, c4 = i & 15;
            float4 v = *(const float4*)(Bsrc + (j0 + r) * 128 + c4 * 4);
            Bs[r][c4 * 4 + 0] = v.x; Bs[r][c4 * 4 + 1] = v.y;
            Bs[r][c4 * 4 + 2] = v.z; Bs[r][c4 * 4 + 3] = v.w;
        }
        __syncthreads();
#pragma unroll 4
        for (int k = 0; k < 64; k++) {
            float a[8], b[4];
#pragma unroll
            for (int i = 0; i < 8; i++) a[i] = As[ty * 8 + i][k];
#pragma unroll
            for (int j = 0; j < 4; j++) b[j] = Bs[tx * 4 + j][k];
#pragma unroll
            for (int i = 0; i < 8; i++)
#pragma unroll
                for (int j = 0; j < 4; j++) acc[i][j] = fmaf(a[i], b[j], acc[i][j]);
        }
        __syncthreads();
    }
#pragma unroll
    for (int i = 0; i < 8; i++) {
        float4 v = make_float4(acc[i][0], acc[i][1], acc[i][2], acc[i][3]);
        *(float4*)&g_gates[(m0 + ty * 8 + i) * 512 + j0 + tx * 4] = v;
    }
}

// ---------------- K4b: LSTM elementwise -> hn ----------------------------
__global__ void k_hn(const float* __restrict__ c0,
                     const float* __restrict__ b_ih,
                     const float* __restrict__ b_hh) {
    int idx = blockIdx.x * 256 + threadIdx.x;   // 1024*128
    if (idx >= NAGT * RNN) return;
    int n = idx >> 7, k = idx & 127;
    const float* gr = g_gates + n * 512;
    float iv = gr[k]       + b_ih[k]       + b_hh[k];
    float fv = gr[128 + k] + b_ih[128 + k] + b_hh[128 + k];
    float gv = gr[256 + k] + b_ih[256 + k] + b_hh[256 + k];
    float ov = gr[384 + k] + b_ih[384 + k] + b_hh[384 + k];
    float si = 1.0f / (1.0f + expf(-iv));
    float sf = 1.0f / (1.0f + expf(-fv));
    float so = 1.0f / (1.0f + expf(-ov));
    float c  = sf * c0[idx] + si * tanhf(gv);
    g_hn[idx] = so * tanhf(c);
}

// ---------------- K4c: out = hn @ W_out^T + b_out, split-layout store ----
// GEMM M=1024 x N=120 x K=128. grid=16, 240 threads, micro 8x4
__global__ void k_out(const float* __restrict__ Wout,
                      const float* __restrict__ b_out,
                      float* __restrict__ out) {
    __shared__ float Hn[64][65];
    __shared__ float Wo[120][65];
    const int m0 = blockIdx.x * 64;
    const int tid = threadIdx.x;   // 240
    const int tx = tid % 30;       // 30 * 4 = 120 cols
    const int ty = tid / 30;       // 8 * 8 = 64 rows

    float acc[8][4];
#pragma unroll
    for (int i = 0; i < 8; i++)
#pragma unroll
        for (int j = 0; j < 4; j++) acc[i][j] = 0.0f;

    for (int kc = 0; kc < 2; kc++) {
        const int kbase = kc * 64;
        for (int i = tid; i < 64 * 16; i += 240) {
            int r = i >> 4, c4 = i & 15;
            float4 v = *(const float4*)(g_hn + (m0 + r) * 128 + kbase + c4 * 4);
            Hn[r][c4 * 4 + 0] = v.x; Hn[r][c4 * 4 + 1] = v.y;
            Hn[r][c4 * 4 + 2] = v.z; Hn[r][c4 * 4 + 3] = v.w;
        }
        for (int i = tid; i < 120 * 16; i += 240) {
            int r = i >> 4, c4 = i & 15;
            float4 v = *(const float4*)(Wout + r * 128 + kbase + c4 * 4);
            Wo[r][c4 * 4 + 0] = v.x; Wo[r][c4 * 4 + 1] = v.y;
            Wo[r][c4 * 4 + 2] = v.z; Wo[r][c4 * 4 + 3] = v.w;
        }
        __syncthreads();
#pragma unroll 4
        for (int k = 0; k < 64; k++) {
            float a[8], b[4];
#pragma unroll
            for (int i = 0; i < 8; i++) a[i] = Hn[ty * 8 + i][k];
#pragma unroll
            for (int j = 0; j < 4; j++) b[j] = Wo[tx * 4 + j][k];
#pragma unroll
            for (int i = 0; i < 8; i++)
#pragma unroll
                for (int j = 0; j < 4; j++) acc[i][j] = fmaf(a[i], b[j], acc[i][j]);
        }
        __syncthreads();
    }
#pragma unroll
    for (int i = 0; i < 8; i++) {
        int n = m0 + ty * 8 + i;
#pragma unroll
        for (int j = 0; j < 4; j++) {
            int col = tx * 4 + j;
            float v = acc[i][j] + b_out[col];
            // output tuple layout: 6 arrays of (1024, 20), concatenated
            out[(col / 20) * (NAGT * NMIX) + n * NMIX + (col % 20)] = v;
        }
    }
}

// ---------------- launch ----------------
extern "C" void kernel_launch(void* const* d_in, const int* in_sizes, int n_in,
                              void* d_out, int out_size) {
    const float* xoff  = (const float*)d_in[0];
    const float* xabs  = (const float*)d_in[1];
    const float* h0    = (const float*)d_in[2];
    const float* c0    = (const float*)d_in[3];
    const float* W_emb = (const float*)d_in[4];
    const float* b_emb = (const float*)d_in[5];
    const float* W_soc = (const float*)d_in[6];
    const float* b_soc = (const float*)d_in[7];
    const float* W_ih  = (const float*)d_in[8];
    const float* W_hh  = (const float*)d_in[9];
    const float* b_ih  = (const float*)d_in[10];
    const float* b_hh  = (const float*)d_in[11];
    const float* W_out = (const float*)d_in[12];
    const float* b_out = (const float*)d_in[13];
    float* out = (float*)d_out;

    k_emb<<<(NAGT * EMB + 255) / 256, 256>>>(xoff, W_emb, b_emb);
    k_hs<<<dim3(16, 64), 128>>>(h0, W_soc);
    k_pool<<<NAGT, 256>>>(xabs, b_soc);
    k_gates<<<dim3(16, 8), 128>>>(h0, W_ih, W_hh);
    k_hn<<<(NAGT * RNN + 255) / 256, 256>>>(c0, b_ih, b_hh);
    k_out<<<16, 240>>>(W_out, b_out, out);
}

// round 2
// speedup vs baseline: 1.1475x; 1.1475x over previous
#include <cuda_runtime.h>
#include <cuda_bf16.h>
#include <math.h>

#define NAGT 1024
#define RNN  128
#define EMB  64
#define GCELLS 64   // 8x8
#define NMIX 20

typedef unsigned long long ull;

// ---------------- device scratch (no allocations allowed) ----------------
__device__ float g_xin[NAGT * 128];          // [emb(64) | pool(64)] per agent
__device__ float g_Hs[NAGT * GCELLS * EMB];  // Hs[m][g][e], 16 MB
__device__ float g_gatesA[NAGT * 512];       // partial: xin @ W_ih^T
__device__ float g_gatesB[NAGT * 512];       // partial: h0  @ W_hh^T
__device__ float g_hn[NAGT * RNN];

// ---------------- f32x2 helpers ----------------
__device__ __forceinline__ void ffma2(ull& d, ull a, ull b) {
    asm("fma.rn.f32x2 %0, %1, %2, %0;" : "+l"(d) : "l"(a), "l"(b));
}
__device__ __forceinline__ float2 unpack2(ull v) {
    float2 r;
    asm("mov.b64 {%0,%1}, %2;" : "=f"(r.x), "=f"(r.y) : "l"(v));
    return r;
}
__device__ __forceinline__ ull dup2(float x) {
    ull r;
    asm("mov.b64 %0, {%1,%1};" : "=l"(r) : "f"(x));
    return r;
}

// swizzled column index for B tile: guarantees conflict-free paired LDS.64
__device__ __forceinline__ int swz(int e) {
    return ((e >> 2) << 1) + ((e & 2) << 4) + (e & 1);
}

// ---------------- K1: emb = relu(xoff @ W_emb^T + b_emb) ----------------
__global__ void k_emb(const float* __restrict__ xoff,
                      const float* __restrict__ W_emb,
                      const float* __restrict__ b_emb) {
    int idx = blockIdx.x * 256 + threadIdx.x;   // 1024*64
    if (idx >= NAGT * EMB) return;
    int n = idx >> 6, e = idx & 63;
    float v = b_emb[e];
    v = fmaf(xoff[2 * n + 0], W_emb[2 * e + 0], v);
    v = fmaf(xoff[2 * n + 1], W_emb[2 * e + 1], v);
    g_xin[n * 128 + e] = fmaxf(v, 0.0f);
}

// ============ shared FFMA2 GEMM tile core =================================
// 64(m) x 64(cols) tile, K processed in chunks of 32, 128 threads, micro 8x4.
// AsD: [row][2k] duplicated pairs, stride 66.  Bs: [k][swz(e)], stride 66.
// Asrc: row-major stride astride; Bsrc: row-major stride bstride (per out col).
// Accumulators owned by caller via acc[8][2] ull.
struct TileSmem {
    float AsD[64 * 66];
    float Bs[32 * 66];
};

__device__ __forceinline__ void gemm_chunk(
    TileSmem& s, const float* __restrict__ Asrc, int astride,
    const float* __restrict__ Bsrc, int bstride,
    int m0, int kb, int tid, int tx, int ty, ull acc[8][2])
{
#pragma unroll
    for (int p = 0; p < 4; p++) {
        int idx = tid + p * 128;           // 512 float4 = 64 rows x 32 k
        int r = idx >> 3, c4 = idx & 7;
        float4 v = *(const float4*)(Asrc + (m0 + r) * astride + kb + c4 * 4);
        int base = r * 66 + c4 * 8;        // (c4*4)*2
        *(ull*)&s.AsD[base + 0] = dup2(v.x);
        *(ull*)&s.AsD[base + 2] = dup2(v.y);
        *(ull*)&s.AsD[base + 4] = dup2(v.z);
        *(ull*)&s.AsD[base + 6] = dup2(v.w);
    }
#pragma unroll
    for (int p = 0; p < 4; p++) {
        int idx = tid + p * 128;           // 64 e-rows x 32 k
        int e = idx >> 3, c4 = idx & 7;
        float4 v = *(const float4*)(Bsrc + e * bstride + kb + c4 * 4);
        int se = swz(e);
        s.Bs[(c4 * 4 + 0) * 66 + se] = v.x;
        s.Bs[(c4 * 4 + 1) * 66 + se] = v.y;
        s.Bs[(c4 * 4 + 2) * 66 + se] = v.z;
        s.Bs[(c4 * 4 + 3) * 66 + se] = v.w;
    }
    __syncthreads();
#pragma unroll 8
    for (int k = 0; k < 32; k++) {
        ull b0 = *(const ull*)&s.Bs[k * 66 + tx * 2];
        ull b1 = *(const ull*)&s.Bs[k * 66 + tx * 2 + 32];
#pragma unroll
        for (int i = 0; i < 8; i++) {
            ull a = *(const ull*)&s.AsD[(ty * 8 + i) * 66 + 2 * k];
            ffma2(acc[i][0], a, b0);
            ffma2(acc[i][1], a, b1);
        }
    }
    __syncthreads();
}

// ---------------- K2: Hs[m,g,e] = sum_h h0[m,h] * W_soc[e, g*128+h] ------
// grid=(16 m-tiles, 64 g), 128 threads
__global__ void __launch_bounds__(128) k_hs(const float* __restrict__ h0,
                                            const float* __restrict__ Wsoc) {
    __shared__ __align__(16) TileSmem s;
    const int m0 = blockIdx.x * 64;
    const int g  = blockIdx.y;
    const int tid = threadIdx.x;
    const int tx = tid & 15;
    const int ty = tid >> 4;

    ull acc[8][2];
#pragma unroll
    for (int i = 0; i < 8; i++) { acc[i][0] = 0ull; acc[i][1] = 0ull; }

#pragma unroll 1
    for (int kc = 0; kc < 4; kc++) {
        gemm_chunk(s, h0, 128, Wsoc + g * 128, 8192, m0, kc * 32, tid, tx, ty, acc);
    }
#pragma unroll
    for (int i = 0; i < 8; i++) {
        float2 p0 = unpack2(acc[i][0]);
        float2 p1 = unpack2(acc[i][1]);
        float4 v = make_float4(p0.x, p0.y, p1.x, p1.y);
        *(float4*)&g_Hs[(m0 + ty * 8 + i) * 4096 + g * 64 + tx * 4] = v;
    }
}

// ---------------- K3: pool[n] = relu(b_soc + sum_m valid * Hs[m,cell,:]) --
__global__ void k_pool(const float* __restrict__ xabs,
                       const float* __restrict__ b_soc) {
    __shared__ float sx[NAGT];
    __shared__ float sy[NAGT];
    __shared__ float red[4][64];
    const int n = blockIdx.x;
    const int tid = threadIdx.x;
    for (int i = tid; i < NAGT; i += 256) {
        sx[i] = xabs[2 * i + 0];
        sy[i] = xabs[2 * i + 1];
    }
    __syncthreads();
    const float xn = sx[n] - 0.2f;   // x[n] - NS/2
    const float yn = sy[n] - 0.2f;
    const int grp = tid >> 6;
    const int e   = tid & 63;
    float acc = 0.0f;
    const int mEnd = grp * 256 + 256;
    for (int m = grp * 256; m < mEnd; ++m) {
        float dx = sx[m] - xn;
        float dy = sy[m] - yn;
        if (m != n && dx >= 0.0f && dx < 0.4f && dy >= 0.0f && dy < 0.4f) {
            int cx = (int)floorf(dx * 20.0f);   // dx/0.4*8
            int cy = (int)floorf(dy * 20.0f);
            if (cx >= 0 && cx < 8 && cy >= 0 && cy < 8) {
                acc += g_Hs[m * 4096 + (cx + cy * 8) * 64 + e];
            }
        }
    }
    red[grp][e] = acc;
    __syncthreads();
    if (tid < 64) {
        float s = red[0][tid] + red[1][tid] + red[2][tid] + red[3][tid] + b_soc[tid];
        g_xin[n * 128 + 64 + tid] = fmaxf(s, 0.0f);
    }
}

// ---------------- K4a: gate partials, K-split z: 0 -> xin@Wih, 1 -> h0@Whh
// grid=(16,8,2), 128 threads
__global__ void __launch_bounds__(128) k_gates(const float* __restrict__ h0,
                                               const float* __restrict__ Wih,
                                               const float* __restrict__ Whh) {
    __shared__ __align__(16) TileSmem s;
    const int m0 = blockIdx.x * 64;
    const int j0 = blockIdx.y * 64;
    const int z  = blockIdx.z;
    const int tid = threadIdx.x;
    const int tx = tid & 15;
    const int ty = tid >> 4;

    const float* Asrc = z ? h0 : g_xin;
    const float* Bsrc = (z ? Whh : Wih) + j0 * 128;
    float* dst = z ? g_gatesB : g_gatesA;

    ull acc[8][2];
#pragma unroll
    for (int i = 0; i < 8; i++) { acc[i][0] = 0ull; acc[i][1] = 0ull; }

#pragma unroll 1
    for (int kc = 0; kc < 4; kc++) {
        gemm_chunk(s, Asrc, 128, Bsrc, 128, m0, kc * 32, tid, tx, ty, acc);
    }
#pragma unroll
    for (int i = 0; i < 8; i++) {
        float2 p0 = unpack2(acc[i][0]);
        float2 p1 = unpack2(acc[i][1]);
        float4 v = make_float4(p0.x, p0.y, p1.x, p1.y);
        *(float4*)&dst[(m0 + ty * 8 + i) * 512 + j0 + tx * 4] = v;
    }
}

// ---------------- K4b: LSTM elementwise -> hn ----------------------------
__global__ void k_hn(const float* __restrict__ c0,
                     const float* __restrict__ b_ih,
                     const float* __restrict__ b_hh) {
    int idx = blockIdx.x * 256 + threadIdx.x;   // 1024*128
    if (idx >= NAGT * RNN) return;
    int n = idx >> 7, k = idx & 127;
    const float* ga = g_gatesA + n * 512;
    const float* gb = g_gatesB + n * 512;
    float iv = ga[k]       + gb[k]       + b_ih[k]       + b_hh[k];
    float fv = ga[128 + k] + gb[128 + k] + b_ih[128 + k] + b_hh[128 + k];
    float gv = ga[256 + k] + gb[256 + k] + b_ih[256 + k] + b_hh[256 + k];
    float ov = ga[384 + k] + gb[384 + k] + b_ih[384 + k] + b_hh[384 + k];
    float si = 1.0f / (1.0f + expf(-iv));
    float sf = 1.0f / (1.0f + expf(-fv));
    float so = 1.0f / (1.0f + expf(-ov));
    float c  = sf * c0[idx] + si * tanhf(gv);
    g_hn[idx] = so * tanhf(c);
}

// ---------------- K4c: out = hn @ W_out^T + b_out, split-layout store ----
__global__ void k_out(const float* __restrict__ Wout,
                      const float* __restrict__ b_out,
                      float* __restrict__ out) {
    __shared__ float Hn[64][65];
    __shared__ float Wo[120][65];
    const int m0 = blockIdx.x * 64;
    const int tid = threadIdx.x;   // 240
    const int tx = tid % 30;
    const int ty = tid / 30;

    float acc[8][4];
#pragma unroll
    for (int i = 0; i < 8; i++)
#pragma unroll
        for (int j = 0; j < 4; j++) acc[i][j] = 0.0f;

    for (int kc = 0; kc < 2; kc++) {
        const int kbase = kc * 64;
        for (int i = tid; i < 64 * 16; i += 240) {
            int r = i >> 4, c4 = i & 15;
            float4 v = *(const float4*)(g_hn + (m0 + r) * 128 + kbase + c4 * 4);
            Hn[r][c4 * 4 + 0] = v.x; Hn[r][c4 * 4 + 1] = v.y;
            Hn[r][c4 * 4 + 2] = v.z; Hn[r][c4 * 4 + 3] = v.w;
        }
        for (int i = tid; i < 120 * 16; i += 240) {
            int r = i >> 4, c4 = i & 15;
            float4 v = *(const float4*)(Wout + r * 128 + kbase + c4 * 4);
            Wo[r][c4 * 4 + 0] = v.x; Wo[r][c4 * 4 + 1] = v.y;
            Wo[r][c4 * 4 + 2] = v.z; Wo[r][c4 * 4 + 3] = v.w;
        }
        __syncthreads();
#pragma unroll 4
        for (int k = 0; k < 64; k++) {
            float a[8], b[4];
#pragma unroll
            for (int i = 0; i < 8; i++) a[i] = Hn[ty * 8 + i][k];
#pragma unroll
            for (int j = 0; j < 4; j++) b[j] = Wo[tx * 4 + j][k];
#pragma unroll
            for (int i = 0; i < 8; i++)
#pragma unroll
                for (int j = 0; j < 4; j++) acc[i][j] = fmaf(a[i], b[j], acc[i][j]);
        }
        __syncthreads();
    }
#pragma unroll
    for (int i = 0; i < 8; i++) {
        int n = m0 + ty * 8 + i;
#pragma unroll
        for (int j = 0; j < 4; j++) {
            int col = tx * 4 + j;
            float v = acc[i][j] + b_out[col];
            out[(col / 20) * (NAGT * NMIX) + n * NMIX + (col % 20)] = v;
        }
    }
}

// ---------------- launch ----------------
extern "C" void kernel_launch(void* const* d_in, const int* in_sizes, int n_in,
                              void* d_out, int out_size) {
    const float* xoff  = (const float*)d_in[0];
    const float* xabs  = (const float*)d_in[1];
    const float* h0    = (const float*)d_in[2];
    const float* c0    = (const float*)d_in[3];
    const float* W_emb = (const float*)d_in[4];
    const float* b_emb = (const float*)d_in[5];
    const float* W_soc = (const float*)d_in[6];
    const float* b_soc = (const float*)d_in[7];
    const float* W_ih  = (const float*)d_in[8];
    const float* W_hh  = (const float*)d_in[9];
    const float* b_ih  = (const float*)d_in[10];
    const float* b_hh  = (const float*)d_in[11];
    const float* W_out = (const float*)d_in[12];
    const float* b_out = (const float*)d_in[13];
    float* out = (float*)d_out;

    k_emb<<<(NAGT * EMB + 255) / 256, 256>>>(xoff, W_emb, b_emb);
    k_hs<<<dim3(16, 64), 128>>>(h0, W_soc);
    k_pool<<<NAGT, 256>>>(xabs, b_soc);
    k_gates<<<dim3(16, 8, 2), 128>>>(h0, W_ih, W_hh);
    k_hn<<<(NAGT * RNN + 255) / 256, 256>>>(c0, b_ih, b_hh);
    k_out<<<16, 240>>>(W_out, b_out, out);
}

// round 3
// speedup vs baseline: 1.6597x; 1.4464x over previous
#include <cuda_runtime.h>
#include <cuda_bf16.h>
#include <math.h>

#define NAGT 1024
#define RNN  128
#define NMIX 20

typedef unsigned long long ull;

// ---------------- device scratch ----------------
__device__ float g_xin[NAGT * 128];          // [emb(64) | pool(64)]
__device__ float g_Hs[NAGT * 64 * 64];       // Hs[m][g][e], 16 MB
__device__ float g_gatesA[NAGT * 512];
__device__ float g_gatesB[NAGT * 512];
__device__ float g_hn[NAGT * RNN];

// ---------------- f32x2 helpers ----------------
__device__ __forceinline__ void ffma2(ull& d, ull a, ull b) {
    asm("fma.rn.f32x2 %0, %1, %2, %0;" : "+l"(d) : "l"(a), "l"(b));
}
__device__ __forceinline__ float2 unpack2(ull v) {
    float2 r;
    asm("mov.b64 {%0,%1}, %2;" : "=f"(r.x), "=f"(r.y) : "l"(v));
    return r;
}
__device__ __forceinline__ ull dup2(float x) {
    ull r;
    asm("mov.b64 %0, {%1,%1};" : "=l"(r) : "f"(x));
    return r;
}

// ============ GEMM core: tile 64(m) x 128(n), K chunked by 32 ============
// 256 threads: ty=tid>>4 (16 groups of 4 rows), tx=tid&15 (cols 2tx+32j+{0,1})
// As: [m][2k] duplicated pairs, stride 66.   Bs: [k][c] natural, stride 130.
struct GSmem {
    float As[64 * 66];    // 16896 B
    float Bs[32 * 130];   // 16640 B
};

__device__ __forceinline__ void fill_A(GSmem& s, const float* __restrict__ Aptr,
                                       int m0, int kb, int tid) {
#pragma unroll
    for (int p = 0; p < 2; p++) {
        int idx = tid + p * 256;          // 512 float4 = 64 m x 8 k4
        int k4 = idx & 7, m = idx >> 3;
        float4 v = *(const float4*)(Aptr + (m0 + m) * 128 + kb + k4 * 4);
        int base = m * 66 + k4 * 8;
        *(ull*)&s.As[base + 0] = dup2(v.x);
        *(ull*)&s.As[base + 2] = dup2(v.y);
        *(ull*)&s.As[base + 4] = dup2(v.z);
        *(ull*)&s.As[base + 6] = dup2(v.w);
    }
}

__device__ __forceinline__ void compute_chunk(GSmem& s, int tx, int ty, ull acc[4][4]) {
#pragma unroll 4
    for (int k = 0; k < 32; k++) {
        ull b[4];
#pragma unroll
        for (int j = 0; j < 4; j++)
            b[j] = *(const ull*)&s.Bs[k * 130 + 2 * tx + 32 * j];
#pragma unroll
        for (int i = 0; i < 4; i++) {
            ull a = *(const ull*)&s.As[(ty * 4 + i) * 66 + 2 * k];
#pragma unroll
            for (int j = 0; j < 4; j++) ffma2(acc[i][j], a, b[j]);
        }
    }
}

// ---------------- K2: Hs  grid=(16 m-tiles, 32 g-pairs) ------------------
__global__ void __launch_bounds__(256) k_hs(const float* __restrict__ h0,
                                            const float* __restrict__ Wsoc) {
    __shared__ __align__(16) GSmem s;
    const int m0 = blockIdx.x * 64;
    const int g0 = blockIdx.y * 2;
    const int tid = threadIdx.x;
    const int tx = tid & 15, ty = tid >> 4;

    ull acc[4][4];
#pragma unroll
    for (int i = 0; i < 4; i++)
#pragma unroll
        for (int j = 0; j < 4; j++) acc[i][j] = 0ull;

#pragma unroll 1
    for (int kc = 0; kc < 4; kc++) {
        const int kb = kc * 32;
        fill_A(s, h0, m0, kb, tid);
#pragma unroll
        for (int p = 0; p < 4; p++) {
            int idx = tid + p * 256;      // 1024 float4 = 128 c x 8 k4
            int k4 = idx & 7, c = idx >> 3;
            float4 v = *(const float4*)(Wsoc + (c & 63) * 8192 +
                                        (g0 + (c >> 6)) * 128 + kb + k4 * 4);
            s.Bs[(k4 * 4 + 0) * 130 + c] = v.x;
            s.Bs[(k4 * 4 + 1) * 130 + c] = v.y;
            s.Bs[(k4 * 4 + 2) * 130 + c] = v.z;
            s.Bs[(k4 * 4 + 3) * 130 + c] = v.w;
        }
        __syncthreads();
        compute_chunk(s, tx, ty, acc);
        __syncthreads();
    }
#pragma unroll
    for (int i = 0; i < 4; i++) {
        int m = m0 + ty * 4 + i;
#pragma unroll
        for (int j = 0; j < 4; j++) {
            int c0 = 2 * tx + 32 * j;
            float2 v = unpack2(acc[i][j]);
            *(float2*)&g_Hs[m * 4096 + (g0 + (c0 >> 6)) * 64 + (c0 & 63)] = v;
        }
    }
}

// ---------------- K4a: gates  grid=(16 m, 4 n, 2 z) ----------------------
__global__ void __launch_bounds__(256) k_gates(const float* __restrict__ h0,
                                               const float* __restrict__ Wih,
                                               const float* __restrict__ Whh) {
    __shared__ __align__(16) GSmem s;
    const int m0 = blockIdx.x * 64;
    const int j0 = blockIdx.y * 128;
    const int z  = blockIdx.z;
    const int tid = threadIdx.x;
    const int tx = tid & 15, ty = tid >> 4;

    const float* Aptr = z ? h0 : g_xin;
    const float* Bw   = (z ? Whh : Wih) + j0 * 128;
    float* dst = z ? g_gatesB : g_gatesA;

    ull acc[4][4];
#pragma unroll
    for (int i = 0; i < 4; i++)
#pragma unroll
        for (int j = 0; j < 4; j++) acc[i][j] = 0ull;

#pragma unroll 1
    for (int kc = 0; kc < 4; kc++) {
        const int kb = kc * 32;
        fill_A(s, Aptr, m0, kb, tid);
#pragma unroll
        for (int p = 0; p < 4; p++) {
            int idx = tid + p * 256;
            int k4 = idx & 7, c = idx >> 3;
            float4 v = *(const float4*)(Bw + c * 128 + kb + k4 * 4);
            s.Bs[(k4 * 4 + 0) * 130 + c] = v.x;
            s.Bs[(k4 * 4 + 1) * 130 + c] = v.y;
            s.Bs[(k4 * 4 + 2) * 130 + c] = v.z;
            s.Bs[(k4 * 4 + 3) * 130 + c] = v.w;
        }
        __syncthreads();
        compute_chunk(s, tx, ty, acc);
        __syncthreads();
    }
#pragma unroll
    for (int i = 0; i < 4; i++) {
        int m = m0 + ty * 4 + i;
#pragma unroll
        for (int j = 0; j < 4; j++) {
            int c0 = 2 * tx + 32 * j;
            float2 v = unpack2(acc[i][j]);
            *(float2*)&dst[m * 512 + j0 + c0] = v;
        }
    }
}

// ---------------- K3: pool (+ fused emb), grid=1024 ----------------------
__global__ void __launch_bounds__(256) k_pool(const float* __restrict__ xabs,
                                              const float* __restrict__ b_soc,
                                              const float* __restrict__ xoff,
                                              const float* __restrict__ W_emb,
                                              const float* __restrict__ b_emb) {
    __shared__ float sx[NAGT];
    __shared__ float sy[NAGT];
    __shared__ unsigned short list[NAGT];
    __shared__ unsigned s_cnt[8];
    __shared__ float red[4][64];
    const int n = blockIdx.x;
    const int tid = threadIdx.x;

    // fused emb for this agent (64 threads)
    if (tid < 64) {
        float v = b_emb[tid];
        v = fmaf(xoff[2 * n + 0], W_emb[2 * tid + 0], v);
        v = fmaf(xoff[2 * n + 1], W_emb[2 * tid + 1], v);
        g_xin[n * 128 + tid] = fmaxf(v, 0.0f);
    }

    for (int i = tid; i < NAGT; i += 256) {
        float2 p = *(const float2*)(xabs + 2 * i);
        sx[i] = p.x; sy[i] = p.y;
    }
    __syncthreads();

    const float xn = sx[n] - 0.2f;
    const float yn = sy[n] - 0.2f;
    const int lane = tid & 31, w = tid >> 5;

    // phase 1: ballot-compacted neighbor list (segment w covers m in [128w,128w+128))
    unsigned cnt = 0;
#pragma unroll
    for (int t = 0; t < 4; t++) {
        int m = w * 128 + t * 32 + lane;
        float dx = sx[m] - xn;
        float dy = sy[m] - yn;
        bool v = (m != n) && dx >= 0.0f && dx < 0.4f && dy >= 0.0f && dy < 0.4f;
        int cell = 0;
        if (v) {
            int cx = (int)floorf(dx * 20.0f);
            int cy = (int)floorf(dy * 20.0f);
            v = (cx >= 0) && (cx < 8) && (cy >= 0) && (cy < 8);
            cell = cx + cy * 8;
        }
        unsigned mask = __ballot_sync(0xffffffffu, v);
        if (v) {
            int pos = cnt + __popc(mask & ((1u << lane) - 1u));
            list[w * 128 + pos] = (unsigned short)((m << 6) | cell);
        }
        cnt += __popc(mask);
    }
    if (lane == 0) s_cnt[w] = cnt;
    __syncthreads();

    // phase 2: gather-sum over compact list; 4 groups x 64 e-lanes
    const int grp = tid >> 6;
    const int e   = tid & 63;
    float acc = 0.0f;
#pragma unroll
    for (int ws = grp * 2; ws < grp * 2 + 2; ws++) {
        int c = s_cnt[ws];
        for (int i = 0; i < c; i++) {
            unsigned v = list[ws * 128 + i];
            acc += g_Hs[(v >> 6) * 4096 + (v & 63) * 64 + e];
        }
    }
    red[grp][e] = acc;
    __syncthreads();
    if (tid < 64) {
        float sum = red[0][tid] + red[1][tid] + red[2][tid] + red[3][tid] + b_soc[tid];
        g_xin[n * 128 + 64 + tid] = fmaxf(sum, 0.0f);
    }
}

// ---------------- K4b: LSTM elementwise -> hn ----------------------------
__global__ void k_hn(const float* __restrict__ c0,
                     const float* __restrict__ b_ih,
                     const float* __restrict__ b_hh) {
    int idx = blockIdx.x * 256 + threadIdx.x;
    if (idx >= NAGT * RNN) return;
    int n = idx >> 7, k = idx & 127;
    const float* ga = g_gatesA + n * 512;
    const float* gb = g_gatesB + n * 512;
    float iv = ga[k]       + gb[k]       + b_ih[k]       + b_hh[k];
    float fv = ga[128 + k] + gb[128 + k] + b_ih[128 + k] + b_hh[128 + k];
    float gv = ga[256 + k] + gb[256 + k] + b_ih[256 + k] + b_hh[256 + k];
    float ov = ga[384 + k] + gb[384 + k] + b_ih[384 + k] + b_hh[384 + k];
    float si = 1.0f / (1.0f + expf(-iv));
    float sf = 1.0f / (1.0f + expf(-fv));
    float so = 1.0f / (1.0f + expf(-ov));
    float c  = sf * c0[idx] + si * tanhf(gv);
    g_hn[idx] = so * tanhf(c);
}

// ---------------- K4c: out GEMM + split-layout store ---------------------
__global__ void k_out(const float* __restrict__ Wout,
                      const float* __restrict__ b_out,
                      float* __restrict__ out) {
    __shared__ float Hn[64][65];
    __shared__ float Wo[120][65];
    const int m0 = blockIdx.x * 64;
    const int tid = threadIdx.x;   // 240
    const int tx = tid % 30;
    const int ty = tid / 30;

    float acc[8][4];
#pragma unroll
    for (int i = 0; i < 8; i++)
#pragma unroll
        for (int j = 0; j < 4; j++) acc[i][j] = 0.0f;

    for (int kc = 0; kc < 2; kc++) {
        const int kbase = kc * 64;
        for (int i = tid; i < 64 * 16; i += 240) {
            int r = i >> 4, c4 = i & 15;
            float4 v = *(const float4*)(g_hn + (m0 + r) * 128 + kbase + c4 * 4);
            Hn[r][c4 * 4 + 0] = v.x; Hn[r][c4 * 4 + 1] = v.y;
            Hn[r][c4 * 4 + 2] = v.z; Hn[r][c4 * 4 + 3] = v.w;
        }
        for (int i = tid; i < 120 * 16; i += 240) {
            int r = i >> 4, c4 = i & 15;
            float4 v = *(const float4*)(Wout + r * 128 + kbase + c4 * 4);
            Wo[r][c4 * 4 + 0] = v.x; Wo[r][c4 * 4 + 1] = v.y;
            Wo[r][c4 * 4 + 2] = v.z; Wo[r][c4 * 4 + 3] = v.w;
        }
        __syncthreads();
#pragma unroll 4
        for (int k = 0; k < 64; k++) {
            float a[8], b[4];
#pragma unroll
            for (int i = 0; i < 8; i++) a[i] = Hn[ty * 8 + i][k];
#pragma unroll
            for (int j = 0; j < 4; j++) b[j] = Wo[tx * 4 + j][k];
#pragma unroll
            for (int i = 0; i < 8; i++)
#pragma unroll
                for (int j = 0; j < 4; j++) acc[i][j] = fmaf(a[i], b[j], acc[i][j]);
        }
        __syncthreads();
    }
#pragma unroll
    for (int i = 0; i < 8; i++) {
        int n = m0 + ty * 8 + i;
#pragma unroll
        for (int j = 0; j < 4; j++) {
            int col = tx * 4 + j;
            float v = acc[i][j] + b_out[col];
            out[(col / 20) * (NAGT * NMIX) + n * NMIX + (col % 20)] = v;
        }
    }
}

// ---------------- launch ----------------
extern "C" void kernel_launch(void* const* d_in, const int* in_sizes, int n_in,
                              void* d_out, int out_size) {
    const float* xoff  = (const float*)d_in[0];
    const float* xabs  = (const float*)d_in[1];
    const float* h0    = (const float*)d_in[2];
    const float* c0    = (const float*)d_in[3];
    const float* W_emb = (const float*)d_in[4];
    const float* b_emb = (const float*)d_in[5];
    const float* W_soc = (const float*)d_in[6];
    const float* b_soc = (const float*)d_in[7];
    const float* W_ih  = (const float*)d_in[8];
    const float* W_hh  = (const float*)d_in[9];
    const float* b_ih  = (const float*)d_in[10];
    const float* b_hh  = (const float*)d_in[11];
    const float* W_out = (const float*)d_in[12];
    const float* b_out = (const float*)d_in[13];
    float* out = (float*)d_out;

    k_hs<<<dim3(16, 32), 256>>>(h0, W_soc);
    k_pool<<<NAGT, 256>>>(xabs, b_soc, xoff, W_emb, b_emb);
    k_gates<<<dim3(16, 4, 2), 256>>>(h0, W_ih, W_hh);
    k_hn<<<(NAGT * RNN + 255) / 256, 256>>>(c0, b_ih, b_hh);
    k_out<<<16, 240>>>(W_out, b_out, out);
}

// round 5
// speedup vs baseline: 2.2803x; 1.3739x over previous
#include <cuda_runtime.h>
#include <cuda_bf16.h>
#include <math.h>
#include <cstdint>

#define NAGT 1024
#define RNN  128
#define NMIX 20

typedef unsigned long long ull;
typedef unsigned int uint;

// ---------------- device scratch ----------------
__device__ float g_xin[NAGT * 128];          // [emb(64) | pool(64)]
__device__ float g_Hs[NAGT * 4096];          // Hs[m][g*64+e], 16 MB
__device__ float g_gatesA[NAGT * 512];
__device__ float g_gatesB[NAGT * 512];
__device__ float g_hn[NAGT * RNN];

// ================= K2: Hs via mma.sync bf16-split GEMM ===================
// C[1024,4096] = h0[1024,128] @ B^T,  B[c,k] = Wsoc[c&63, (c>>6)*128+k]
// 3-term split: Ahi*Bhi + Ahi*Blo + Alo*Bhi, f32 accum.
// Tile 128m x 256n, K=128 resident. 512 thr (16 warps, 4x4), warp 32m x 64n.
// smem rows padded to 272 B for conflict-free fragment LDS.
#define HS_AROW 272                    // bytes per A row (128 bf16 + 8 pad)
#define HS_A_HI 0
#define HS_A_LO (128 * HS_AROW)        // 34816
#define HS_B_HI (2 * 128 * HS_AROW)    // 69632
#define HS_B_LO (HS_B_HI + 256 * HS_AROW)
#define HS_SMEM (HS_B_LO + 256 * HS_AROW)   // 208896

__device__ __forceinline__ uint pack_hi2(float x, float y, float& lx, float& ly) {
    __nv_bfloat16 hx = __float2bfloat16(x);
    __nv_bfloat16 hy = __float2bfloat16(y);
    lx = x - __bfloat162float(hx);
    ly = y - __bfloat162float(hy);
    __nv_bfloat162 h; h.x = hx; h.y = hy;
    return *(uint*)&h;
}
__device__ __forceinline__ uint pack2(float x, float y) {
    __nv_bfloat162 h; h.x = __float2bfloat16(x); h.y = __float2bfloat16(y);
    return *(uint*)&h;
}

__device__ __forceinline__ void mma16816(float* d, uint a0, uint a1, uint a2, uint a3,
                                         uint b0, uint b1) {
    asm volatile(
        "mma.sync.aligned.m16n8k16.row.col.f32.bf16.bf16.f32 "
        "{%0,%1,%2,%3}, {%4,%5,%6,%7}, {%8,%9}, {%0,%1,%2,%3};"
        : "+f"(d[0]), "+f"(d[1]), "+f"(d[2]), "+f"(d[3])
        : "r"(a0), "r"(a1), "r"(a2), "r"(a3), "r"(b0), "r"(b1));
}

__global__ void __launch_bounds__(512) k_hs_tc(const float* __restrict__ h0,
                                               const float* __restrict__ Wsoc) {
    extern __shared__ __align__(16) char sm[];
    const int tid = threadIdx.x;
    const int wid = tid >> 5, lane = tid & 31;
    const int m0 = blockIdx.x * 128;
    const int c0 = blockIdx.y * 256;

    // ---- fill A: 128 x 128 fp32 -> bf16 hi/lo ----
#pragma unroll
    for (int p = 0; p < 8; p++) {
        int idx = tid + p * 512;            // 4096 float4 = 128 rows x 32
        int r = idx >> 5, c4 = idx & 31;
        float4 v = *(const float4*)(h0 + (m0 + r) * 128 + c4 * 4);
        float lx, ly, lz, lw;
        uint2 H, L;
        H.x = pack_hi2(v.x, v.y, lx, ly);
        H.y = pack_hi2(v.z, v.w, lz, lw);
        L.x = pack2(lx, ly);
        L.y = pack2(lz, lw);
        int off = r * HS_AROW + c4 * 8;
        *(uint2*)(sm + HS_A_HI + off) = H;
        *(uint2*)(sm + HS_A_LO + off) = L;
    }
    // ---- fill B: 256 x 128 ----
#pragma unroll
    for (int p = 0; p < 16; p++) {
        int idx = tid + p * 512;            // 8192 float4 = 256 rows x 32
        int r = idx >> 5, c4 = idx & 31;
        int gc = c0 + r;
        float4 v = *(const float4*)(Wsoc + (gc & 63) * 8192 + (gc >> 6) * 128 + c4 * 4);
        float lx, ly, lz, lw;
        uint2 H, L;
        H.x = pack_hi2(v.x, v.y, lx, ly);
        H.y = pack_hi2(v.z, v.w, lz, lw);
        L.x = pack2(lx, ly);
        L.y = pack2(lz, lw);
        int off = r * HS_AROW + c4 * 8;
        *(uint2*)(sm + HS_B_HI + off) = H;
        *(uint2*)(sm + HS_B_LO + off) = L;
    }
    __syncthreads();

    const int wm = (wid >> 2) * 32;        // warp m offset (0..96)
    const int wn = (wid & 3) * 64;         // warp n offset (0..192)
    const int tq = lane >> 2;              // t/4: row-in-tile
    const int tr = lane & 3;               // t%4: col pair group

    float acc[2][8][4];
#pragma unroll
    for (int i = 0; i < 2; i++)
#pragma unroll
        for (int j = 0; j < 8; j++)
#pragma unroll
            for (int q = 0; q < 4; q++) acc[i][j][q] = 0.0f;

#pragma unroll 1
    for (int ks = 0; ks < 8; ks++) {
        const int kb = ks * 32 + tr * 4;   // byte offset of this lane's k pair
        // A fragments: 2 m-tiles x {hi,lo} x 4 regs
        uint aH[2][4], aL[2][4];
#pragma unroll
        for (int mf = 0; mf < 2; mf++) {
            int row = wm + mf * 16 + tq;
            int o0 = row * HS_AROW + kb;
            int o1 = o0 + 8 * HS_AROW;
            aH[mf][0] = *(const uint*)(sm + HS_A_HI + o0);
            aH[mf][1] = *(const uint*)(sm + HS_A_HI + o1);
            aH[mf][2] = *(const uint*)(sm + HS_A_HI + o0 + 16);
            aH[mf][3] = *(const uint*)(sm + HS_A_HI + o1 + 16);
            aL[mf][0] = *(const uint*)(sm + HS_A_LO + o0);
            aL[mf][1] = *(const uint*)(sm + HS_A_LO + o1);
            aL[mf][2] = *(const uint*)(sm + HS_A_LO + o0 + 16);
            aL[mf][3] = *(const uint*)(sm + HS_A_LO + o1 + 16);
        }
#pragma unroll
        for (int nf = 0; nf < 8; nf++) {
            int col = wn + nf * 8 + tq;
            int o0 = col * HS_AROW + kb;
            uint bH0 = *(const uint*)(sm + HS_B_HI + o0);
            uint bH1 = *(const uint*)(sm + HS_B_HI + o0 + 16);
            uint bL0 = *(const uint*)(sm + HS_B_LO + o0);
            uint bL1 = *(const uint*)(sm + HS_B_LO + o0 + 16);
#pragma unroll
            for (int mf = 0; mf < 2; mf++) {
                mma16816(acc[mf][nf], aH[mf][0], aH[mf][1], aH[mf][2], aH[mf][3], bH0, bH1);
                mma16816(acc[mf][nf], aH[mf][0], aH[mf][1], aH[mf][2], aH[mf][3], bL0, bL1);
                mma16816(acc[mf][nf], aL[mf][0], aL[mf][1], aL[mf][2], aL[mf][3], bH0, bH1);
            }
        }
    }

    // ---- epilogue: direct f32 stores ----
#pragma unroll
    for (int mf = 0; mf < 2; mf++) {
        int row0 = m0 + wm + mf * 16 + tq;
#pragma unroll
        for (int nf = 0; nf < 8; nf++) {
            int col = c0 + wn + nf * 8 + tr * 2;
            *(float2*)&g_Hs[row0 * 4096 + col] =
                make_float2(acc[mf][nf][0], acc[mf][nf][1]);
            *(float2*)&g_Hs[(row0 + 8) * 4096 + col] =
                make_float2(acc[mf][nf][2], acc[mf][nf][3]);
        }
    }
}

// ================= FFMA2 GEMM core (for gates) ============================
__device__ __forceinline__ void ffma2(ull& d, ull a, ull b) {
    asm("fma.rn.f32x2 %0, %1, %2, %0;" : "+l"(d) : "l"(a), "l"(b));
}
__device__ __forceinline__ float2 unpack2(ull v) {
    float2 r;
    asm("mov.b64 {%0,%1}, %2;" : "=f"(r.x), "=f"(r.y) : "l"(v));
    return r;
}
__device__ __forceinline__ ull dup2(float x) {
    ull r;
    asm("mov.b64 %0, {%1,%1};" : "=l"(r) : "f"(x));
    return r;
}
struct GSmem {
    float As[64 * 66];
    float Bs[32 * 130];
};
__device__ __forceinline__ void fill_A(GSmem& s, const float* __restrict__ Aptr,
                                       int m0, int kb, int tid) {
#pragma unroll
    for (int p = 0; p < 2; p++) {
        int idx = tid + p * 256;
        int k4 = idx & 7, m = idx >> 3;
        float4 v = *(const float4*)(Aptr + (m0 + m) * 128 + kb + k4 * 4);
        int base = m * 66 + k4 * 8;
        *(ull*)&s.As[base + 0] = dup2(v.x);
        *(ull*)&s.As[base + 2] = dup2(v.y);
        *(ull*)&s.As[base + 4] = dup2(v.z);
        *(ull*)&s.As[base + 6] = dup2(v.w);
    }
}
__device__ __forceinline__ void compute_chunk(GSmem& s, int tx, int ty, ull acc[4][4]) {
#pragma unroll 4
    for (int k = 0; k < 32; k++) {
        ull b[4];
#pragma unroll
        for (int j = 0; j < 4; j++)
            b[j] = *(const ull*)&s.Bs[k * 130 + 2 * tx + 32 * j];
#pragma unroll
        for (int i = 0; i < 4; i++) {
            ull a = *(const ull*)&s.As[(ty * 4 + i) * 66 + 2 * k];
#pragma unroll
            for (int j = 0; j < 4; j++) ffma2(acc[i][j], a, b[j]);
        }
    }
}

// ---------------- K4a: gates  grid=(16 m, 4 n, 2 z) ----------------------
__global__ void __launch_bounds__(256) k_gates(const float* __restrict__ h0,
                                               const float* __restrict__ Wih,
                                               const float* __restrict__ Whh) {
    __shared__ __align__(16) GSmem s;
    const int m0 = blockIdx.x * 64;
    const int j0 = blockIdx.y * 128;
    const int z  = blockIdx.z;
    const int tid = threadIdx.x;
    const int tx = tid & 15, ty = tid >> 4;

    const float* Aptr = z ? h0 : g_xin;
    const float* Bw   = (z ? Whh : Wih) + j0 * 128;
    float* dst = z ? g_gatesB : g_gatesA;

    ull acc[4][4];
#pragma unroll
    for (int i = 0; i < 4; i++)
#pragma unroll
        for (int j = 0; j < 4; j++) acc[i][j] = 0ull;

#pragma unroll 1
    for (int kc = 0; kc < 4; kc++) {
        const int kb = kc * 32;
        fill_A(s, Aptr, m0, kb, tid);
#pragma unroll
        for (int p = 0; p < 4; p++) {
            int idx = tid + p * 256;
            int k4 = idx & 7, c = idx >> 3;
            float4 v = *(const float4*)(Bw + c * 128 + kb + k4 * 4);
            s.Bs[(k4 * 4 + 0) * 130 + c] = v.x;
            s.Bs[(k4 * 4 + 1) * 130 + c] = v.y;
            s.Bs[(k4 * 4 + 2) * 130 + c] = v.z;
            s.Bs[(k4 * 4 + 3) * 130 + c] = v.w;
        }
        __syncthreads();
        compute_chunk(s, tx, ty, acc);
        __syncthreads();
    }
#pragma unroll
    for (int i = 0; i < 4; i++) {
        int m = m0 + ty * 4 + i;
#pragma unroll
        for (int j = 0; j < 4; j++) {
            int c0 = 2 * tx + 32 * j;
            float2 v = unpack2(acc[i][j]);
            *(float2*)&dst[m * 512 + j0 + c0] = v;
        }
    }
}

// ---------------- K3: pool (+ fused emb), grid=1024 ----------------------
__global__ void __launch_bounds__(256) k_pool(const float* __restrict__ xabs,
                                              const float* __restrict__ b_soc,
                                              const float* __restrict__ xoff,
                                              const float* __restrict__ W_emb,
                                              const float* __restrict__ b_emb) {
    __shared__ float sx[NAGT];
    __shared__ float sy[NAGT];
    __shared__ unsigned short list[NAGT];
    __shared__ unsigned s_cnt[8];
    __shared__ float red[4][64];
    const int n = blockIdx.x;
    const int tid = threadIdx.x;

    if (tid < 64) {
        float v = b_emb[tid];
        v = fmaf(xoff[2 * n + 0], W_emb[2 * tid + 0], v);
        v = fmaf(xoff[2 * n + 1], W_emb[2 * tid + 1], v);
        g_xin[n * 128 + tid] = fmaxf(v, 0.0f);
    }
    for (int i = tid; i < NAGT; i += 256) {
        float2 p = *(const float2*)(xabs + 2 * i);
        sx[i] = p.x; sy[i] = p.y;
    }
    __syncthreads();

    const float xn = sx[n] - 0.2f;
    const float yn = sy[n] - 0.2f;
    const int lane = tid & 31, w = tid >> 5;

    unsigned cnt = 0;
#pragma unroll
    for (int t = 0; t < 4; t++) {
        int m = w * 128 + t * 32 + lane;
        float dx = sx[m] - xn;
        float dy = sy[m] - yn;
        bool v = (m != n) && dx >= 0.0f && dx < 0.4f && dy >= 0.0f && dy < 0.4f;
        int cell = 0;
        if (v) {
            int cx = (int)floorf(dx * 20.0f);
            int cy = (int)floorf(dy * 20.0f);
            v = (cx >= 0) && (cx < 8) && (cy >= 0) && (cy < 8);
            cell = cx + cy * 8;
        }
        unsigned mask = __ballot_sync(0xffffffffu, v);
        if (v) {
            int pos = cnt + __popc(mask & ((1u << lane) - 1u));
            list[w * 128 + pos] = (unsigned short)((m << 6) | cell);
        }
        cnt += __popc(mask);
    }
    if (lane == 0) s_cnt[w] = cnt;
    __syncthreads();

    const int grp = tid >> 6;
    const int e   = tid & 63;
    float acc = 0.0f;
#pragma unroll
    for (int ws = grp * 2; ws < grp * 2 + 2; ws++) {
        int c = s_cnt[ws];
        for (int i = 0; i < c; i++) {
            unsigned v = list[ws * 128 + i];
            acc += g_Hs[(v >> 6) * 4096 + (v & 63) * 64 + e];
        }
    }
    red[grp][e] = acc;
    __syncthreads();
    if (tid < 64) {
        float sum = red[0][tid] + red[1][tid] + red[2][tid] + red[3][tid] + b_soc[tid];
        g_xin[n * 128 + 64 + tid] = fmaxf(sum, 0.0f);
    }
}

// ---------------- K4b: LSTM elementwise -> hn (float4) -------------------
__global__ void k_hn(const float* __restrict__ c0v,
                     const float* __restrict__ b_ih,
                     const float* __restrict__ b_hh) {
    int idx = blockIdx.x * 256 + threadIdx.x;   // 1024*32
    if (idx >= NAGT * 32) return;
    int n = idx >> 5, k = (idx & 31) * 4;
    const float* ga = g_gatesA + n * 512;
    const float* gb = g_gatesB + n * 512;
    float4 r;
#pragma unroll
    for (int q = 0; q < 4; q++) {
        float iv = ga[k+q]       + gb[k+q]       + b_ih[k+q]       + b_hh[k+q];
        float fv = ga[128+k+q]   + gb[128+k+q]   + b_ih[128+k+q]   + b_hh[128+k+q];
        float gv = ga[256+k+q]   + gb[256+k+q]   + b_ih[256+k+q]   + b_hh[256+k+q];
        float ov = ga[384+k+q]   + gb[384+k+q]   + b_ih[384+k+q]   + b_hh[384+k+q];
        float si = 1.0f / (1.0f + expf(-iv));
        float sf = 1.0f / (1.0f + expf(-fv));
        float so = 1.0f / (1.0f + expf(-ov));
        float c  = sf * c0v[n * 128 + k + q] + si * tanhf(gv);
        ((float*)&r)[q] = so * tanhf(c);
    }
    *(float4*)(g_hn + n * 128 + k) = r;
}

// ---------------- K4c: out GEMM + split-layout store ---------------------
__global__ void k_out(const float* __restrict__ Wout,
                      const float* __restrict__ b_out,
                      float* __restrict__ out) {
    __shared__ float Hn[64][65];
    __shared__ float Wo[120][65];
    const int m0 = blockIdx.x * 64;
    const int tid = threadIdx.x;   // 240
    const int tx = tid % 30;
    const int ty = tid / 30;

    float acc[8][4];
#pragma unroll
    for (int i = 0; i < 8; i++)
#pragma unroll
        for (int j = 0; j < 4; j++) acc[i][j] = 0.0f;

    for (int kc = 0; kc < 2; kc++) {
        const int kbase = kc * 64;
        for (int i = tid; i < 64 * 16; i += 240) {
            int r = i >> 4, c4 = i & 15;
            float4 v = *(const float4*)(g_hn + (m0 + r) * 128 + kbase + c4 * 4);
            Hn[r][c4 * 4 + 0] = v.x; Hn[r][c4 * 4 + 1] = v.y;
            Hn[r][c4 * 4 + 2] = v.z; Hn[r][c4 * 4 + 3] = v.w;
        }
        for (int i = tid; i < 120 * 16; i += 240) {
            int r = i >> 4, c4 = i & 15;
            float4 v = *(const float4*)(Wout + r * 128 + kbase + c4 * 4);
            Wo[r][c4 * 4 + 0] = v.x; Wo[r][c4 * 4 + 1] = v.y;
            Wo[r][c4 * 4 + 2] = v.z; Wo[r][c4 * 4 + 3] = v.w;
        }
        __syncthreads();
#pragma unroll 4
        for (int k = 0; k < 64; k++) {
            float a[8], b[4];
#pragma unroll
            for (int i = 0; i < 8; i++) a[i] = Hn[ty * 8 + i][k];
#pragma unroll
            for (int j = 0; j < 4; j++) b[j] = Wo[tx * 4 + j][k];
#pragma unroll
            for (int i = 0; i < 8; i++)
#pragma unroll
                for (int j = 0; j < 4; j++) acc[i][j] = fmaf(a[i], b[j], acc[i][j]);
        }
        __syncthreads();
    }
#pragma unroll
    for (int i = 0; i < 8; i++) {
        int n = m0 + ty * 8 + i;
#pragma unroll
        for (int j = 0; j < 4; j++) {
            int col = tx * 4 + j;
            float v = acc[i][j] + b_out[col];
            out[(col / 20) * (NAGT * NMIX) + n * NMIX + (col % 20)] = v;
        }
    }
}

// ---------------- launch ----------------
extern "C" void kernel_launch(void* const* d_in, const int* in_sizes, int n_in,
                              void* d_out, int out_size) {
    const float* xoff  = (const float*)d_in[0];
    const float* xabs  = (const float*)d_in[1];
    const float* h0    = (const float*)d_in[2];
    const float* c0    = (const float*)d_in[3];
    const float* W_emb = (const float*)d_in[4];
    const float* b_emb = (const float*)d_in[5];
    const float* W_soc = (const float*)d_in[6];
    const float* b_soc = (const float*)d_in[7];
    const float* W_ih  = (const float*)d_in[8];
    const float* W_hh  = (const float*)d_in[9];
    const float* b_ih  = (const float*)d_in[10];
    const float* b_hh  = (const float*)d_in[11];
    const float* W_out = (const float*)d_in[12];
    const float* b_out = (const float*)d_in[13];
    float* out = (float*)d_out;

    cudaFuncSetAttribute(k_hs_tc, cudaFuncAttributeMaxDynamicSharedMemorySize, HS_SMEM);

    k_hs_tc<<<dim3(8, 16), 512, HS_SMEM>>>(h0, W_soc);
    k_pool<<<NAGT, 256>>>(xabs, b_soc, xoff, W_emb, b_emb);
    k_gates<<<dim3(16, 4, 2), 256>>>(h0, W_ih, W_hh);
    k_hn<<<128, 256>>>(c0, b_ih, b_hh);
    k_out<<<16, 240>>>(W_out, b_out, out);
}